// round 1
// baseline (speedup 1.0000x reference)
#include <cuda_runtime.h>
#include <cuda_bf16.h>

// Problem constants
#define BB 4
#define PP 64
#define SS 8
#define YD 16
#define GD 48
#define NOUT (BB*PP*PP*SS*SS)          // 1,048,576 outputs
#define NTAB (BB*PP*SS)                // 2048 entries in c1/c2 tables

// Precomputed per-(b,p,s) linear terms
__device__ float g_c1[NTAB];
__device__ float g_c2[NTAB];

// ---------------------------------------------------------------------------
// Prep: c1[b,p,s] = y[b,p,s,:]·Wy[0:16],  c2 = y·Wy[16:32]
// ---------------------------------------------------------------------------
__global__ void prep_kernel(const float* __restrict__ y,
                            const float* __restrict__ Wy) {
    int idx = blockIdx.x * blockDim.x + threadIdx.x;
    if (idx >= NTAB) return;
    const float* yr = y + (size_t)idx * YD;
    float a = 0.f, b = 0.f;
#pragma unroll
    for (int k = 0; k < YD; ++k) {
        float v = yr[k];
        a = fmaf(v, Wy[k], a);
        b = fmaf(v, Wy[YD + k], b);
    }
    g_c1[idx] = a;
    g_c2[idx] = b;
}

// ---------------------------------------------------------------------------
// Main: each warp handles 32 consecutive outputs.
//   - coalesced float4 load of the warp's 6KB contiguous g region
//   - stage into smem with row stride 56 floats (16B-aligned, low conflict)
//   - each lane dots its own 48 floats vs register-resident Wg
// ---------------------------------------------------------------------------
#define WARPS_PER_BLOCK 4
#define ROW_STRIDE 56                    // floats; 224B = multiple of 16B

__global__ __launch_bounds__(32 * WARPS_PER_BLOCK)
void main_kernel(const float* __restrict__ g,
                 const float* __restrict__ Wg,
                 const float* __restrict__ bg,
                 const float* __restrict__ by,
                 float* __restrict__ out) {
    __shared__ float smem[WARPS_PER_BLOCK][32 * ROW_STRIDE];

    const int lane   = threadIdx.x & 31;
    const int warpIn = threadIdx.x >> 5;
    const int warp   = blockIdx.x * WARPS_PER_BLOCK + warpIn;
    const int base   = warp * 32;                 // first output of this tile
    if (base >= NOUT) return;

    // Load Wg into registers (12x float4, L1/L2 resident)
    float w[GD];
    {
        const float4* wv = (const float4*)Wg;
#pragma unroll
        for (int c = 0; c < GD / 4; ++c) {
            float4 t = __ldg(&wv[c]);
            w[4*c+0] = t.x; w[4*c+1] = t.y; w[4*c+2] = t.z; w[4*c+3] = t.w;
        }
    }
    const float bias = __ldg(bg) + __ldg(by);

    // ---- Stage: 32 outputs * 48 floats = 384 float4, coalesced ----
    float* sw = smem[warpIn];
    const float4* gs = (const float4*)(g + (size_t)base * GD);
#pragma unroll
    for (int k = 0; k < 12; ++k) {
        int f = lane + 32 * k;                    // float4 index 0..383
        float4 v = gs[f];
        int row = f / 12;                         // output-within-tile
        int col = (f % 12) * 4;                   // float offset in row
        *(float4*)(sw + row * ROW_STRIDE + col) = v;
    }
    __syncwarp();

    // ---- Compute: lane -> output (base+lane) ----
    const float* gr = sw + lane * ROW_STRIDE;
    float a0 = 0.f, a1 = 0.f, a2 = 0.f, a3 = 0.f;
#pragma unroll
    for (int c = 0; c < 12; ++c) {
        float4 t = *(const float4*)(gr + 4 * c);
        a0 = fmaf(t.x, w[4*c+0], a0);
        a1 = fmaf(t.y, w[4*c+1], a1);
        a2 = fmaf(t.z, w[4*c+2], a2);
        a3 = fmaf(t.w, w[4*c+3], a3);
    }
    float sum = (a0 + a1) + (a2 + a3) + bias;

    // Broadcast terms: o = ((((b*P+i)*P+j)*S+si)*S+sj)
    int o  = base + lane;
    int sj = o & 7;
    int si = (o >> 3) & 7;
    int j  = (o >> 6) & 63;
    int i  = (o >> 12) & 63;
    int b  = o >> 18;
    sum += g_c1[((b << 6) + j) * SS + sj];        // ky1[b, j, sj]
    sum += g_c2[((b << 6) + i) * SS + si];        // ky2[b, i, si]

    out[o] = sum;
}

// ---------------------------------------------------------------------------
// Launch
// inputs (metadata order): y(32768), pairwise_g(50331648), Wy(32), by(1),
//                          Wg(48), bg(1)
// ---------------------------------------------------------------------------
extern "C" void kernel_launch(void* const* d_in, const int* in_sizes, int n_in,
                              void* d_out, int out_size) {
    const float* y  = (const float*)d_in[0];
    const float* g  = (const float*)d_in[1];
    const float* Wy = (const float*)d_in[2];
    const float* by = (const float*)d_in[3];
    const float* Wg = (const float*)d_in[4];
    const float* bg = (const float*)d_in[5];
    float* out = (float*)d_out;

    prep_kernel<<<(NTAB + 255) / 256, 256>>>(y, Wy);

    const int tiles  = NOUT / 32;                         // 32768 warps
    const int blocks = tiles / WARPS_PER_BLOCK;           // 8192
    main_kernel<<<blocks, 32 * WARPS_PER_BLOCK>>>(g, Wg, bg, by, out);
}

// round 2
// speedup vs baseline: 1.2723x; 1.2723x over previous
#include <cuda_runtime.h>
#include <cuda_bf16.h>

// Problem constants
#define BB 4
#define PP 64
#define SS 8
#define YD 16
#define GD 48
#define NOUT (BB*PP*PP*SS*SS)          // 1,048,576 outputs
#define NTAB (BB*PP*SS)                // 2048 entries in c1/c2 tables

// Precomputed per-(b,p,s) linear terms (bias folded into c1)
__device__ float g_c1[NTAB];
__device__ float g_c2[NTAB];

// ---------------------------------------------------------------------------
// Prep: c1[b,p,s] = y[b,p,s,:]·Wy[0:16] + bg + by,  c2 = y·Wy[16:32]
// ---------------------------------------------------------------------------
__global__ void prep_kernel(const float* __restrict__ y,
                            const float* __restrict__ Wy,
                            const float* __restrict__ by,
                            const float* __restrict__ bg) {
    int idx = blockIdx.x * blockDim.x + threadIdx.x;
    if (idx >= NTAB) return;
    const float* yr = y + (size_t)idx * YD;
    float a = 0.f, b = 0.f;
#pragma unroll
    for (int k = 0; k < YD; ++k) {
        float v = yr[k];
        a = fmaf(v, Wy[k], a);
        b = fmaf(v, Wy[YD + k], b);
    }
    g_c1[idx] = a + by[0] + bg[0];
    g_c2[idx] = b;
}

// ---------------------------------------------------------------------------
// Main: each warp handles 32 consecutive outputs (one 6KB tile of g).
//   - 12 perfectly coalesced LDG.128 (lane l takes float4 f = l + 32k)
//   - float4 f needs weight column f%12 = (l%12 + 8k)%12; since 8k%12 cycles
//     {0,8,4}, each lane uses only 3 weight float4s, held in registers and
//     selected statically by k%3.
//   - each lane reduces its float4 to a scalar partial -> smem (384 floats,
//     conflict-free STS.32)
//   - lane r sums its row's 12 partials via 3 conflict-free LDS.128
// ---------------------------------------------------------------------------
#define WARPS_PER_BLOCK 8

__device__ __forceinline__ float dot4(float4 v, float4 w) {
    return fmaf(v.x, w.x, fmaf(v.y, w.y, fmaf(v.z, w.z, v.w * w.w)));
}

__global__ __launch_bounds__(32 * WARPS_PER_BLOCK)
void main_kernel(const float* __restrict__ g,
                 const float* __restrict__ Wg,
                 float* __restrict__ out) {
    __shared__ float part[WARPS_PER_BLOCK][12 * 32];

    const int lane = threadIdx.x & 31;
    const int wIn  = threadIdx.x >> 5;
    const int warp = blockIdx.x * WARPS_PER_BLOCK + wIn;
    const int base = warp * 32;

    // The 3 weight columns this lane ever needs (k%3 == 0,1,2 -> A,B,C)
    const int l12 = lane % 12;
    int cB = l12 + 8; if (cB >= 12) cB -= 12;
    int cC = l12 + 4; if (cC >= 12) cC -= 12;
    const float4* wv = (const float4*)Wg;
    const float4 wA = __ldg(wv + l12);
    const float4 wB = __ldg(wv + cB);
    const float4 wC = __ldg(wv + cC);

    const float4* gs = (const float4*)(g + (size_t)base * GD);
    float* p = part[wIn];

    // ---- batch 1: k = 0..5 (6 loads in flight) ----
    float4 v0 = gs[lane +   0];
    float4 v1 = gs[lane +  32];
    float4 v2 = gs[lane +  64];
    float4 v3 = gs[lane +  96];
    float4 v4 = gs[lane + 128];
    float4 v5 = gs[lane + 160];
    p[lane +   0] = dot4(v0, wA);
    p[lane +  32] = dot4(v1, wB);
    p[lane +  64] = dot4(v2, wC);
    p[lane +  96] = dot4(v3, wA);
    p[lane + 128] = dot4(v4, wB);
    p[lane + 160] = dot4(v5, wC);

    // ---- batch 2: k = 6..11 ----
    float4 u0 = gs[lane + 192];
    float4 u1 = gs[lane + 224];
    float4 u2 = gs[lane + 256];
    float4 u3 = gs[lane + 288];
    float4 u4 = gs[lane + 320];
    float4 u5 = gs[lane + 352];
    p[lane + 192] = dot4(u0, wA);
    p[lane + 224] = dot4(u1, wB);
    p[lane + 256] = dot4(u2, wC);
    p[lane + 288] = dot4(u3, wA);
    p[lane + 320] = dot4(u4, wB);
    p[lane + 352] = dot4(u5, wC);

    __syncwarp();

    // ---- reduce: lane r owns output base+r, partials at p[12r .. 12r+11] ----
    const float4* pr = (const float4*)(p + lane * 12);   // 48B aligned
    float4 t0 = pr[0], t1 = pr[1], t2 = pr[2];
    float sum = ((t0.x + t0.y) + (t0.z + t0.w))
              + ((t1.x + t1.y) + (t1.z + t1.w))
              + ((t2.x + t2.y) + (t2.z + t2.w));

    // Broadcast terms: o = ((((b*P+i)*P+j)*S+si)*S+sj)
    const int o  = base + lane;
    const int sj = o & 7;
    const int si = (o >> 3) & 7;
    const int j  = (o >> 6) & 63;
    const int i  = (o >> 12) & 63;
    const int b  = o >> 18;
    sum += g_c1[(((b << 6) + j) << 3) + sj];   // ky1[b, j, sj] (+bias)
    sum += g_c2[(((b << 6) + i) << 3) + si];   // ky2[b, i, si]

    out[o] = sum;
}

// ---------------------------------------------------------------------------
// Launch
// inputs (metadata order): y(32768), pairwise_g(50331648), Wy(32), by(1),
//                          Wg(48), bg(1)
// ---------------------------------------------------------------------------
extern "C" void kernel_launch(void* const* d_in, const int* in_sizes, int n_in,
                              void* d_out, int out_size) {
    const float* y  = (const float*)d_in[0];
    const float* g  = (const float*)d_in[1];
    const float* Wy = (const float*)d_in[2];
    const float* by = (const float*)d_in[3];
    const float* Wg = (const float*)d_in[4];
    const float* bg = (const float*)d_in[5];
    float* out = (float*)d_out;

    prep_kernel<<<(NTAB + 255) / 256, 256>>>(y, Wy, by, bg);

    const int tiles  = NOUT / 32;                         // 32768 warps
    const int blocks = tiles / WARPS_PER_BLOCK;           // 4096
    main_kernel<<<blocks, 32 * WARPS_PER_BLOCK>>>(g, Wg, out);
}

// round 3
// speedup vs baseline: 1.3363x; 1.0504x over previous
#include <cuda_runtime.h>
#include <cuda_bf16.h>

// Problem constants
#define BB 4
#define PP 64
#define SS 8
#define YD 16
#define GD 48
#define NOUT (BB*PP*PP*SS*SS)          // 1,048,576 outputs

#define WARPS_PER_BLOCK 8

__device__ __forceinline__ float dot4(float4 v, float4 w) {
    return fmaf(v.x, w.x, fmaf(v.y, w.y, fmaf(v.z, w.z, v.w * w.w)));
}

// ---------------------------------------------------------------------------
// Single fused kernel. Each warp: 32 consecutive outputs = one 6KB tile of g.
//
// Broadcast terms (replaces the old prep kernel):
//   outputs o = ((((b*64+i)*64+j)*8+si)*8+sj); per warp (b,i,j) fixed,
//   sj = lane&7, si = si0 + (lane>>3), si0 = 4*(warp&1).
//   c1[b,j,s] = y[b,j,s,:]·Wy[0:16]; the 8 values come from one contiguous
//   512B row of y -> 1 LDG.128/lane + quad butterfly-reduce + shfl.idx.
//   c2 symmetric with row (b,i) and Wy[16:32].
//
// Main contraction:
//   12 coalesced LDG.128 (lane l -> float4 f = l + 32k); weight column
//   f%12 = (l%12 + 8k)%12 cycles {A,B,C} with k%3, so 3 register float4s.
//   Partials -> smem (conflict-free STS.32), lane r reduces its 12 partials
//   via 3 conflict-free LDS.128.
// ---------------------------------------------------------------------------
__global__ __launch_bounds__(32 * WARPS_PER_BLOCK)
void fused_kernel(const float* __restrict__ y,
                  const float* __restrict__ g,
                  const float* __restrict__ Wy,
                  const float* __restrict__ by,
                  const float* __restrict__ Wg,
                  const float* __restrict__ bg,
                  float* __restrict__ out) {
    __shared__ float part[WARPS_PER_BLOCK][12 * 32];

    const int lane = threadIdx.x & 31;
    const int wIn  = threadIdx.x >> 5;
    const int warp = blockIdx.x * WARPS_PER_BLOCK + wIn;
    const int base = warp * 32;

    // ---- kick off main loads first (batch 1), hide prologue under them ----
    const float4* gs = (const float4*)(g + (size_t)base * GD);
    float4 v0 = __ldcs(gs + lane +   0);
    float4 v1 = __ldcs(gs + lane +  32);
    float4 v2 = __ldcs(gs + lane +  64);
    float4 v3 = __ldcs(gs + lane +  96);
    float4 v4 = __ldcs(gs + lane + 128);
    float4 v5 = __ldcs(gs + lane + 160);

    // ---- broadcast terms: warp-cooperative dots over y rows ----
    const int j = (base >> 6)  & 63;
    const int i = (base >> 12) & 63;
    const int b =  base >> 18;
    const int si0 = (warp & 1) << 2;

    const int q = lane & 3;
    const float4 w1 = *(const float4*)(Wy + 4 * q);          // Wy[0:16] seg q
    const float4 w2 = *(const float4*)(Wy + YD + 4 * q);     // Wy[16:32] seg q
    const float4* rowj = (const float4*)(y + (size_t)((b << 6) + j) * (SS * YD));
    const float4* rowi = (const float4*)(y + (size_t)((b << 6) + i) * (SS * YD));
    float p1 = dot4(rowj[lane], w1);                         // y[b,j, l>>2, 4q..]
    float p2 = dot4(rowi[lane], w2);
    p1 += __shfl_xor_sync(0xffffffffu, p1, 1);
    p1 += __shfl_xor_sync(0xffffffffu, p1, 2);
    p2 += __shfl_xor_sync(0xffffffffu, p2, 1);
    p2 += __shfl_xor_sync(0xffffffffu, p2, 2);
    // c1[s] now in all lanes of quad s; fetch the one this lane needs
    const float c1 = __shfl_sync(0xffffffffu, p1, (lane & 7) << 2);
    const float c2 = __shfl_sync(0xffffffffu, p2, (si0 + (lane >> 3)) << 2);
    const float c12 = c1 + c2 + __ldg(by) + __ldg(bg);

    // ---- per-lane weight columns: (l%12 + {0,8,4}) % 12 ----
    const int l12 = lane % 12;
    int cB = l12 + 8; if (cB >= 12) cB -= 12;
    int cC = l12 + 4; if (cC >= 12) cC -= 12;
    const float4* wv = (const float4*)Wg;
    const float4 wA = __ldg(wv + l12);
    const float4 wB = __ldg(wv + cB);
    const float4 wC = __ldg(wv + cC);

    float* p = part[wIn];

    // ---- batch 1 compute ----
    p[lane +   0] = dot4(v0, wA);
    p[lane +  32] = dot4(v1, wB);
    p[lane +  64] = dot4(v2, wC);
    p[lane +  96] = dot4(v3, wA);
    p[lane + 128] = dot4(v4, wB);
    p[lane + 160] = dot4(v5, wC);

    // ---- batch 2 ----
    float4 u0 = __ldcs(gs + lane + 192);
    float4 u1 = __ldcs(gs + lane + 224);
    float4 u2 = __ldcs(gs + lane + 256);
    float4 u3 = __ldcs(gs + lane + 288);
    float4 u4 = __ldcs(gs + lane + 320);
    float4 u5 = __ldcs(gs + lane + 352);
    p[lane + 192] = dot4(u0, wA);
    p[lane + 224] = dot4(u1, wB);
    p[lane + 256] = dot4(u2, wC);
    p[lane + 288] = dot4(u3, wA);
    p[lane + 320] = dot4(u4, wB);
    p[lane + 352] = dot4(u5, wC);

    __syncwarp();

    // ---- reduce: lane r owns output base+r, partials at p[12r .. 12r+11] ----
    const float4* pr = (const float4*)(p + lane * 12);       // 48B aligned
    float4 t0 = pr[0], t1 = pr[1], t2 = pr[2];
    float sum = ((t0.x + t0.y) + (t0.z + t0.w))
              + ((t1.x + t1.y) + (t1.z + t1.w))
              + ((t2.x + t2.y) + (t2.z + t2.w))
              + c12;

    __stcs(out + base + lane, sum);
}

// ---------------------------------------------------------------------------
// Launch
// inputs (metadata order): y(32768), pairwise_g(50331648), Wy(32), by(1),
//                          Wg(48), bg(1)
// ---------------------------------------------------------------------------
extern "C" void kernel_launch(void* const* d_in, const int* in_sizes, int n_in,
                              void* d_out, int out_size) {
    const float* y  = (const float*)d_in[0];
    const float* g  = (const float*)d_in[1];
    const float* Wy = (const float*)d_in[2];
    const float* by = (const float*)d_in[3];
    const float* Wg = (const float*)d_in[4];
    const float* bg = (const float*)d_in[5];
    float* out = (float*)d_out;

    const int tiles  = NOUT / 32;                 // 32768 warps
    const int blocks = tiles / WARPS_PER_BLOCK;   // 4096
    fused_kernel<<<blocks, 32 * WARPS_PER_BLOCK>>>(y, g, Wy, by, Wg, bg, out);
}